// round 9
// baseline (speedup 1.0000x reference)
#include <cuda_runtime.h>
#include <cuda_bf16.h>
#include <math.h>
#include <stdint.h>

// Problem constants
#define ADIM 8
#define BDIM 16
#define HDIM 64
#define WDIM 64
#define SPATIAL (ADIM*BDIM*HDIM*WDIM)   // 524288
#define COUT 32
#define EPSV 1e-5f
#define NEG_SLOPE 0.2f

// smem plane geometry: 66 rows (input h=-1..64 -> r=h+1), staggered stride.
// base(r) = r*84 + 4*((r>>1)&3); ww maps to col ww+4 (border zeros at col 3, 68).
#define PLSZ 5536          // floats per plane buffer (max used idx 5529)

typedef unsigned long long ull;

// Scratch (static device globals; runtime allocation is forbidden)
__device__ float g_buf1[COUT * SPATIAL];
__device__ float g_buf2[COUT * SPATIAL];
__device__ float2 g_stats1[COUT];
__device__ float2 g_stats2[COUT];

// ---------------------------------------------------------------------------
#define FMA2(d, a, b) \
    asm volatile("fma.rn.f32x2 %0, %1, %2, %0;" : "+l"(d) : "l"(a), "l"(b))

// u = (hi(a), lo(b))  -- unaligned middle pair
#define MIDPAIR(u, a, b) \
    asm volatile("{\n\t.reg .b32 l1, h1, l2, h2;\n\t" \
                 "mov.b64 {l1,h1}, %1;\n\t" \
                 "mov.b64 {l2,h2}, %2;\n\t" \
                 "mov.b64 %0, {h1, l2};\n\t}" \
                 : "=l"(u) : "l"(a), "l"(b))

#define CP_COMMIT() asm volatile("cp.async.commit_group;")
#define CP_WAIT0()  asm volatile("cp.async.wait_group 0;")

__device__ __forceinline__ int rowbase(int r) {
    return r * 84 + (((r >> 1) & 3) << 2);
}

// Interior loader: input rows 0..63 -> smem rows 1..64, cols 4..67.
// 1024 x 16B cp.async per plane = 4 per thread. Fully coalesced, 16B aligned.
__device__ __forceinline__ void load_plane(float* s, const float* xp, int tid)
{
    #pragma unroll
    for (int k = 0; k < 4; ++k) {
        const int e = tid + (k << 8);          // 0..1023
        const int row_i = e >> 4;              // 0..63
        const int v = e & 15;                  // 16B chunk
        const int r = row_i + 1;
        float* d = s + rowbase(r) + 4 + (v << 2);
        uint32_t sa = (uint32_t)__cvta_generic_to_shared(d);
        asm volatile("cp.async.cg.shared.global [%0], [%1], 16;"
                     :: "r"(sa), "l"(xp + row_i * 64 + (v << 2)));
    }
}

// ---------------------------------------------------------------------------
// Direct 4D conv, 3x3x3x3, pad 1, FFMA2 math.
// Block: 256 thr, tile = full 64H x 64W at fixed (a,b), 4 couts (grid.z=8).
// Thread: 2H x 8W x 4co = 32 packed accumulators.
// Staggered smem rows kill LDS bank conflicts; one __syncthreads per ci;
// cp.async.cg 16B double-buffered planes.
// ---------------------------------------------------------------------------
template<int CIN>
__global__ __launch_bounds__(256, 2)
void conv4d_kernel(const float* __restrict__ x,   // [CIN][A][B][H][W]
                   const float* __restrict__ w,   // [COUT][CIN][3][3][3][3]
                   float* __restrict__ y)         // [COUT][A][B][H][W]
{
    extern __shared__ float sm[];
    // [0 .. 2*PLSZ)          : 2 input plane buffers
    // [2*PLSZ .. +CIN*48*2)  : weights as dup-pairs: [ci][kh][co(4)][4 taps pad]
    float2* wsm = reinterpret_cast<float2*>(sm + 2 * PLSZ);

    const int a   = blockIdx.x >> 4;
    const int b   = blockIdx.x & 15;
    const int co0 = blockIdx.z * 4;

    const int tid   = threadIdx.x;
    const int tx    = tid & 7;          // 8 w-groups of 8 px
    const int ty    = tid >> 3;         // 32 h-groups of 2 rows
    const int rbase = ty * 2;           // output rows rbase, rbase+1
    const int wbase = tx * 8;

    // One-time zero of both plane buffers (covers H/W halo borders forever)
    {
        float4* z = reinterpret_cast<float4*>(sm);
        #pragma unroll 4
        for (int i = tid; i < (2 * PLSZ) / 4; i += 256)
            z[i] = make_float4(0.f, 0.f, 0.f, 0.f);
    }

    ull acc[4][2][4] = {};   // [co][ph][w-pair]

    int buf = 0;
    for (int da = 0; da < 3; ++da) {
        const int ia = a + da - 1;
        if ((unsigned)ia >= (unsigned)ADIM) continue;
        for (int db = 0; db < 3; ++db) {
            const int ib = b + db - 1;
            if ((unsigned)ib >= (unsigned)BDIM) continue;

            const float* xab = x + ((size_t)ia * BDIM + ib) * (HDIM * WDIM);

            __syncthreads();   // prior compute done -> wsm & planes reusable

            // Fill dup-pair weights for this (da,db): CIN*48 float2 entries
            const int tap9 = (da * 3 + db) * 9;
            for (int t = tid; t < CIN * 48; t += 256) {
                const int ci   = t / 48;
                const int rem  = t - ci * 48;
                const int kh   = rem >> 4;
                const int rem2 = rem & 15;
                const int co   = rem2 >> 2;
                const int tp   = rem2 & 3;
                float v = 0.f;
                if (tp < 3)
                    v = w[((size_t)(co0 + co) * CIN + ci) * 81 + tap9 + kh * 3 + tp];
                wsm[t] = make_float2(v, v);
            }

            // Prologue: stream plane ci=0 into current buffer
            load_plane(sm + buf * PLSZ, xab, tid);
            CP_COMMIT();

            for (int ci = 0; ci < CIN; ++ci) {
                CP_WAIT0();        // own writes for plane ci landed
                __syncthreads();   // all writes visible; compute(ci-1) finished

                if (ci + 1 < CIN) {   // prefetch next plane into other buffer
                    load_plane(sm + (buf ^ 1) * PLSZ,
                               xab + (size_t)(ci + 1) * SPATIAL, tid);
                    CP_COMMIT();
                }

                const float*  pl  = sm + buf * PLSZ;
                const float2* wci = wsm + ci * 48;

                #pragma unroll
                for (int ir = 0; ir < 4; ++ir) {          // input rows rbase-1..+2
                    const int r = rbase + ir;             // smem row = input h + 1
                    const float* rp = pl + rowbase(r) + wbase + 2;
                    ull al[6], od[5];
                    #pragma unroll
                    for (int i = 0; i < 6; ++i)
                        al[i] = *reinterpret_cast<const ull*>(rp + 2 * i);
                    #pragma unroll
                    for (int k = 0; k < 5; ++k) MIDPAIR(od[k], al[k], al[k + 1]);

                    #pragma unroll
                    for (int ph = 0; ph < 2; ++ph) {
                        const int kh = ir - ph;           // ph0:kh=ir, ph1:kh=ir-1
                        if (kh < 0 || kh > 2) continue;   // resolved at compile time
                        const float2* wk = wci + kh * 16;
                        #pragma unroll
                        for (int co = 0; co < 4; ++co) {
                            uint32_t wa = (uint32_t)__cvta_generic_to_shared(wk + co * 4);
                            ull w0, w1;
                            asm volatile("ld.shared.v2.u64 {%0,%1}, [%2];"
                                         : "=l"(w0), "=l"(w1) : "r"(wa));
                            const ull w2 = *reinterpret_cast<const ull*>(wk + co * 4 + 2);
                            #pragma unroll
                            for (int j = 0; j < 4; ++j) {
                                FMA2(acc[co][ph][j], w0, od[j]);       // kw=0
                                FMA2(acc[co][ph][j], w1, al[j + 1]);   // kw=1
                                FMA2(acc[co][ph][j], w2, od[j + 1]);   // kw=2
                            }
                        }
                    }
                }
                buf ^= 1;
            }
        }
    }

    // Epilogue: 2 x float4 per (co, ph)
    #pragma unroll
    for (int co = 0; co < 4; ++co) {
        float* yb = y + (((size_t)(co0 + co) * ADIM + a) * BDIM + b) * (HDIM * WDIM);
        #pragma unroll
        for (int ph = 0; ph < 2; ++ph) {
            const int h = rbase + ph;
            const float2 v0 = *reinterpret_cast<const float2*>(&acc[co][ph][0]);
            const float2 v1 = *reinterpret_cast<const float2*>(&acc[co][ph][1]);
            const float2 v2 = *reinterpret_cast<const float2*>(&acc[co][ph][2]);
            const float2 v3 = *reinterpret_cast<const float2*>(&acc[co][ph][3]);
            *reinterpret_cast<float4*>(yb + h * WDIM + wbase) =
                make_float4(v0.x, v0.y, v1.x, v1.y);
            *reinterpret_cast<float4*>(yb + h * WDIM + wbase + 4) =
                make_float4(v2.x, v2.y, v3.x, v3.y);
        }
    }
}

// ---------------------------------------------------------------------------
// Per-channel mean / rstd. One block per channel, deterministic.
// ---------------------------------------------------------------------------
__global__ __launch_bounds__(1024)
void stats_kernel(const float* __restrict__ buf, float2* __restrict__ stats)
{
    const int co = blockIdx.x;
    const float4* p = reinterpret_cast<const float4*>(buf + (size_t)co * SPATIAL);
    const int nvec = SPATIAL / 4;

    float s = 0.f, s2 = 0.f;
    for (int i = threadIdx.x; i < nvec; i += 1024) {
        float4 v = p[i];
        s  += v.x + v.y + v.z + v.w;
        s2 += v.x * v.x + v.y * v.y + v.z * v.z + v.w * v.w;
    }
    #pragma unroll
    for (int o = 16; o > 0; o >>= 1) {
        s  += __shfl_down_sync(0xffffffffu, s,  o);
        s2 += __shfl_down_sync(0xffffffffu, s2, o);
    }
    __shared__ float rs[32], rs2[32];
    const int lane = threadIdx.x & 31, wid = threadIdx.x >> 5;
    if (lane == 0) { rs[wid] = s; rs2[wid] = s2; }
    __syncthreads();
    if (wid == 0) {
        s  = rs[lane];
        s2 = rs2[lane];
        #pragma unroll
        for (int o = 16; o > 0; o >>= 1) {
            s  += __shfl_down_sync(0xffffffffu, s,  o);
            s2 += __shfl_down_sync(0xffffffffu, s2, o);
        }
        if (lane == 0) {
            const float inv_n = 1.0f / (float)SPATIAL;
            const float mean  = s * inv_n;
            const float var   = fmaxf(s2 * inv_n - mean * mean, 0.f);
            stats[co] = make_float2(mean, rsqrtf(var + EPSV));
        }
    }
}

// ---------------------------------------------------------------------------
// out = leaky_relu((in - mean) * rstd)
// ---------------------------------------------------------------------------
__global__ __launch_bounds__(256)
void normleaky_kernel(const float* __restrict__ in,
                      const float2* __restrict__ stats,
                      float* __restrict__ out)
{
    const int nvec = COUT * SPATIAL / 4;
    const float4* ip = reinterpret_cast<const float4*>(in);
    float4* op = reinterpret_cast<float4*>(out);
    for (int i = blockIdx.x * blockDim.x + threadIdx.x; i < nvec;
         i += gridDim.x * blockDim.x) {
        const int co = (i * 4) >> 19;
        const float2 st = stats[co];
        float4 v = ip[i];
        float a0 = (v.x - st.x) * st.y;
        float a1 = (v.y - st.x) * st.y;
        float a2 = (v.z - st.x) * st.y;
        float a3 = (v.w - st.x) * st.y;
        v.x = a0 >= 0.f ? a0 : NEG_SLOPE * a0;
        v.y = a1 >= 0.f ? a1 : NEG_SLOPE * a1;
        v.z = a2 >= 0.f ? a2 : NEG_SLOPE * a2;
        v.w = a3 >= 0.f ? a3 : NEG_SLOPE * a3;
        op[i] = v;
    }
}

// ---------------------------------------------------------------------------
extern "C" void kernel_launch(void* const* d_in, const int* in_sizes, int n_in,
                              void* d_out, int out_size)
{
    (void)in_sizes; (void)n_in; (void)out_size;
    const float* image = (const float*)d_in[0];
    const float* w1    = (const float*)d_in[1];
    const float* w2    = (const float*)d_in[2];
    float* out = (float*)d_out;

    float*  buf1; cudaGetSymbolAddress((void**)&buf1, g_buf1);
    float*  buf2; cudaGetSymbolAddress((void**)&buf2, g_buf2);
    float2* st1;  cudaGetSymbolAddress((void**)&st1,  g_stats1);
    float2* st2;  cudaGetSymbolAddress((void**)&st2,  g_stats2);

    const int smem16 = (2 * PLSZ + 16 * 48 * 2) * 4;   // 50432 B
    const int smem32 = (2 * PLSZ + 32 * 48 * 2) * 4;   // 56576 B
    cudaFuncSetAttribute(conv4d_kernel<16>,
                         cudaFuncAttributeMaxDynamicSharedMemorySize, smem16);
    cudaFuncSetAttribute(conv4d_kernel<32>,
                         cudaFuncAttributeMaxDynamicSharedMemorySize, smem32);

    const dim3 cgrid(ADIM * BDIM, 1, COUT / 4);   // (128, 1, 8)

    conv4d_kernel<16><<<cgrid, 256, smem16>>>(image, w1, buf1);
    stats_kernel<<<COUT, 1024>>>(buf1, st1);
    normleaky_kernel<<<2048, 256>>>(buf1, st1, buf1);

    conv4d_kernel<32><<<cgrid, 256, smem32>>>(buf1, w2, buf2);
    stats_kernel<<<COUT, 1024>>>(buf2, st2);
    normleaky_kernel<<<2048, 256>>>(buf2, st2, out);
}

// round 10
// speedup vs baseline: 1.1279x; 1.1279x over previous
#include <cuda_runtime.h>
#include <cuda_bf16.h>
#include <math.h>
#include <stdint.h>

// Problem constants
#define ADIM 8
#define BDIM 16
#define HDIM 64
#define WDIM 64
#define SPATIAL (ADIM*BDIM*HDIM*WDIM)   // 524288
#define COUT 32
#define EPSV 1e-5f
#define NEG_SLOPE 0.2f

// smem plane: 34 rows (input h = h0-1 .. h0+32), stride 72 floats.
// input col ww maps to smem col ww+4 (interior 4..67); cols 0..3 / 68..71 zero.
#define PLSTRIDE 72
#define PLROWS   34
#define PLSZ     (PLROWS * PLSTRIDE)    // 2448 floats

typedef unsigned long long ull;

// Scratch (static device globals; runtime allocation is forbidden)
__device__ float g_buf1[COUT * SPATIAL];
__device__ float g_buf2[COUT * SPATIAL];
__device__ float2 g_stats1[COUT];
__device__ float2 g_stats2[COUT];

// ---------------------------------------------------------------------------
#define FMA2(d, a, b) \
    asm volatile("fma.rn.f32x2 %0, %1, %2, %0;" : "+l"(d) : "l"(a), "l"(b))

// u = (hi(a), lo(b))  -- unaligned middle pair
#define MIDPAIR(u, a, b) \
    asm volatile("{\n\t.reg .b32 l1, h1, l2, h2;\n\t" \
                 "mov.b64 {l1,h1}, %1;\n\t" \
                 "mov.b64 {l2,h2}, %2;\n\t" \
                 "mov.b64 %0, {h1, l2};\n\t}" \
                 : "=l"(u) : "l"(a), "l"(b))

#define CP_COMMIT() asm volatile("cp.async.commit_group;")
#define CP_WAIT0()  asm volatile("cp.async.wait_group 0;")

// Loader: 34 rows x 16 chunks of 16B = 544 cp.async, shift-only indexing.
// OOB rows (hh<0 or hh>=64) zero-filled via src-size 0.
__device__ __forceinline__ void load_plane(float* s, const float* xp,
                                           int h0, int tid)
{
    #pragma unroll
    for (int k = 0; k < 3; ++k) {
        const int e = tid + (k << 8);
        if (e < PLROWS * 16) {
            const int r = e >> 4;           // smem row 0..33
            const int c = e & 15;           // 16B chunk
            const int hh = h0 - 1 + r;
            const bool ok = (unsigned)hh < (unsigned)HDIM;
            uint32_t sa = (uint32_t)__cvta_generic_to_shared(
                              s + r * PLSTRIDE + 4 + (c << 2));
            const float* g = xp + (size_t)(ok ? hh : 0) * WDIM + (c << 2);
            asm volatile("cp.async.cg.shared.global [%0], [%1], 16, %2;"
                         :: "r"(sa), "l"(g), "r"(ok ? 16 : 0));
        }
    }
}

// ---------------------------------------------------------------------------
// Direct 4D conv, 3x3x3x3, pad 1, FFMA2 math.
// Block: 256 thr, tile 32H x 64W at fixed (a,b), 4 couts (grid = 128,2,8).
// Thread: 2H x 4W x 4co -> acc[4][2][2] packed pairs (32 regs).
// __launch_bounds__(256,3): 3 CTAs/SM -> 24 warps to hide LDS latency.
// ---------------------------------------------------------------------------
template<int CIN>
__global__ __launch_bounds__(256, 3)
void conv4d_kernel(const float* __restrict__ x,   // [CIN][A][B][H][W]
                   const float* __restrict__ w,   // [COUT][CIN][3][3][3][3]
                   float* __restrict__ y)         // [COUT][A][B][H][W]
{
    extern __shared__ float sm[];
    // [0 .. 2*PLSZ)        : two input plane buffers
    // [2*PLSZ .. )         : weights, dup-pairs: idx = ci*36 + kh*12 + kw*4 + co
    float2* wsm = reinterpret_cast<float2*>(sm + 2 * PLSZ);

    const int a   = blockIdx.x >> 4;
    const int b   = blockIdx.x & 15;
    const int h0  = blockIdx.y * 32;
    const int co0 = blockIdx.z * 4;

    const int tid   = threadIdx.x;
    const int tx    = tid & 15;          // 4 px in W: 4tx..4tx+3
    const int ty    = tid >> 4;          // 2 rows in H
    const int rbase = ty * 2;            // smem row of (out_h - 1) for ph0,kh0
    const int cb    = tx * 4 + 2;        // aligned pair window start (smem col)

    // One-time zero of border cols (0..3, 68..71) of both buffers.
    // 2 buf x 34 rows x 8 cols = 544 floats.
    #pragma unroll
    for (int k = 0; k < 3; ++k) {
        const int e = tid + (k << 8);
        if (e < 2 * PLROWS * 8) {
            const int bf = e >= PLROWS * 8;
            const int r  = (e - bf * PLROWS * 8) >> 3;
            const int c  = e & 7;
            sm[bf * PLSZ + r * PLSTRIDE + ((c < 4) ? c : (c + 64))] = 0.f;
        }
    }

    ull acc[4][2][2] = {};   // [co][ph][w-pair]

    int buf = 0;
    for (int da = 0; da < 3; ++da) {
        const int ia = a + da - 1;
        if ((unsigned)ia >= (unsigned)ADIM) continue;
        for (int db = 0; db < 3; ++db) {
            const int ib = b + db - 1;
            if ((unsigned)ib >= (unsigned)BDIM) continue;

            const float* xab = x + ((size_t)ia * BDIM + ib) * (HDIM * WDIM);

            __syncthreads();   // prior segment's compute done -> wsm reusable

            // Fill dup-pair weights for all (ci,kh,kw,co) of this (da,db)
            const int tap9 = (da * 3 + db) * 9;
            for (int t = tid; t < CIN * 36; t += 256) {
                const int co  = t & 3;
                const int q   = t >> 2;       // ci*9 + kh*3 + kw
                const int tap = q % 9;
                const int ci  = q / 9;
                const float v = w[((size_t)(co0 + co) * CIN + ci) * 81 + tap9 + tap];
                wsm[t] = make_float2(v, v);
            }

            load_plane(sm + buf * PLSZ, xab, h0, tid);
            CP_COMMIT();

            for (int ci = 0; ci < CIN; ++ci) {
                CP_WAIT0();        // own cp.async writes for plane ci landed
                __syncthreads();   // all writes visible; compute(ci-1) finished

                if (ci + 1 < CIN) {
                    load_plane(sm + (buf ^ 1) * PLSZ,
                               xab + (size_t)(ci + 1) * SPATIAL, h0, tid);
                    CP_COMMIT();
                }

                const float*  pl  = sm + buf * PLSZ;
                const float2* wci = wsm + ci * 36;

                // Row window registers, rolled across kh (fully unrolled).
                ull alA[4], odA[3], alB[4], odB[3];
                {
                    const float* rp = pl + rbase * PLSTRIDE + cb;
                    #pragma unroll
                    for (int m = 0; m < 4; ++m)
                        alA[m] = *reinterpret_cast<const ull*>(rp + 2 * m);
                    #pragma unroll
                    for (int m = 0; m < 3; ++m) MIDPAIR(odA[m], alA[m], alA[m + 1]);
                }

                #pragma unroll
                for (int kh = 0; kh < 3; ++kh) {
                    // B row = input row below A (ph1's kh-tap / next A)
                    const float* rp = pl + (rbase + kh + 1) * PLSTRIDE + cb;
                    #pragma unroll
                    for (int m = 0; m < 4; ++m)
                        alB[m] = *reinterpret_cast<const ull*>(rp + 2 * m);
                    #pragma unroll
                    for (int m = 0; m < 3; ++m) MIDPAIR(odB[m], alB[m], alB[m + 1]);

                    const float2* wk = wci + kh * 12;
                    #pragma unroll
                    for (int kw = 0; kw < 3; ++kw) {
                        #pragma unroll
                        for (int co = 0; co < 4; ++co) {
                            const ull ww = *reinterpret_cast<const ull*>(
                                               wk + kw * 4 + co);   // broadcast
                            #pragma unroll
                            for (int j = 0; j < 2; ++j) {
                                const ull xa = (kw == 0) ? odA[j]
                                             : (kw == 1) ? alA[j + 1] : odA[j + 1];
                                const ull xb = (kw == 0) ? odB[j]
                                             : (kw == 1) ? alB[j + 1] : odB[j + 1];
                                FMA2(acc[co][0][j], ww, xa);
                                FMA2(acc[co][1][j], ww, xb);
                            }
                        }
                    }
                    // roll: A <- B
                    #pragma unroll
                    for (int m = 0; m < 4; ++m) alA[m] = alB[m];
                    #pragma unroll
                    for (int m = 0; m < 3; ++m) odA[m] = odB[m];
                }
                buf ^= 1;
            }
        }
    }

    // Epilogue: one float4 per (co, ph)
    #pragma unroll
    for (int co = 0; co < 4; ++co) {
        float* yb = y + (((size_t)(co0 + co) * ADIM + a) * BDIM + b) * (HDIM * WDIM);
        #pragma unroll
        for (int ph = 0; ph < 2; ++ph) {
            const int h = h0 + rbase + ph;
            const float2 v0 = *reinterpret_cast<const float2*>(&acc[co][ph][0]);
            const float2 v1 = *reinterpret_cast<const float2*>(&acc[co][ph][1]);
            *reinterpret_cast<float4*>(yb + h * WDIM + tx * 4) =
                make_float4(v0.x, v0.y, v1.x, v1.y);
        }
    }
}

// ---------------------------------------------------------------------------
// Per-channel mean / rstd. One block per channel, deterministic.
// ---------------------------------------------------------------------------
__global__ __launch_bounds__(1024)
void stats_kernel(const float* __restrict__ buf, float2* __restrict__ stats)
{
    const int co = blockIdx.x;
    const float4* p = reinterpret_cast<const float4*>(buf + (size_t)co * SPATIAL);
    const int nvec = SPATIAL / 4;

    float s = 0.f, s2 = 0.f;
    for (int i = threadIdx.x; i < nvec; i += 1024) {
        float4 v = p[i];
        s  += v.x + v.y + v.z + v.w;
        s2 += v.x * v.x + v.y * v.y + v.z * v.z + v.w * v.w;
    }
    #pragma unroll
    for (int o = 16; o > 0; o >>= 1) {
        s  += __shfl_down_sync(0xffffffffu, s,  o);
        s2 += __shfl_down_sync(0xffffffffu, s2, o);
    }
    __shared__ float rs[32], rs2[32];
    const int lane = threadIdx.x & 31, wid = threadIdx.x >> 5;
    if (lane == 0) { rs[wid] = s; rs2[wid] = s2; }
    __syncthreads();
    if (wid == 0) {
        s  = rs[lane];
        s2 = rs2[lane];
        #pragma unroll
        for (int o = 16; o > 0; o >>= 1) {
            s  += __shfl_down_sync(0xffffffffu, s,  o);
            s2 += __shfl_down_sync(0xffffffffu, s2, o);
        }
        if (lane == 0) {
            const float inv_n = 1.0f / (float)SPATIAL;
            const float mean  = s * inv_n;
            const float var   = fmaxf(s2 * inv_n - mean * mean, 0.f);
            stats[co] = make_float2(mean, rsqrtf(var + EPSV));
        }
    }
}

// ---------------------------------------------------------------------------
// out = leaky_relu((in - mean) * rstd)
// ---------------------------------------------------------------------------
__global__ __launch_bounds__(256)
void normleaky_kernel(const float* __restrict__ in,
                      const float2* __restrict__ stats,
                      float* __restrict__ out)
{
    const int nvec = COUT * SPATIAL / 4;
    const float4* ip = reinterpret_cast<const float4*>(in);
    float4* op = reinterpret_cast<float4*>(out);
    for (int i = blockIdx.x * blockDim.x + threadIdx.x; i < nvec;
         i += gridDim.x * blockDim.x) {
        const int co = (i * 4) >> 19;
        const float2 st = stats[co];
        float4 v = ip[i];
        float a0 = (v.x - st.x) * st.y;
        float a1 = (v.y - st.x) * st.y;
        float a2 = (v.z - st.x) * st.y;
        float a3 = (v.w - st.x) * st.y;
        v.x = a0 >= 0.f ? a0 : NEG_SLOPE * a0;
        v.y = a1 >= 0.f ? a1 : NEG_SLOPE * a1;
        v.z = a2 >= 0.f ? a2 : NEG_SLOPE * a2;
        v.w = a3 >= 0.f ? a3 : NEG_SLOPE * a3;
        op[i] = v;
    }
}

// ---------------------------------------------------------------------------
extern "C" void kernel_launch(void* const* d_in, const int* in_sizes, int n_in,
                              void* d_out, int out_size)
{
    (void)in_sizes; (void)n_in; (void)out_size;
    const float* image = (const float*)d_in[0];
    const float* w1    = (const float*)d_in[1];
    const float* w2    = (const float*)d_in[2];
    float* out = (float*)d_out;

    float*  buf1; cudaGetSymbolAddress((void**)&buf1, g_buf1);
    float*  buf2; cudaGetSymbolAddress((void**)&buf2, g_buf2);
    float2* st1;  cudaGetSymbolAddress((void**)&st1,  g_stats1);
    float2* st2;  cudaGetSymbolAddress((void**)&st2,  g_stats2);

    const int smem16 = (2 * PLSZ + 16 * 36 * 2) * 4;   // 24192 B
    const int smem32 = (2 * PLSZ + 32 * 36 * 2) * 4;   // 28800 B
    cudaFuncSetAttribute(conv4d_kernel<16>,
                         cudaFuncAttributeMaxDynamicSharedMemorySize, smem16);
    cudaFuncSetAttribute(conv4d_kernel<32>,
                         cudaFuncAttributeMaxDynamicSharedMemorySize, smem32);

    const dim3 cgrid(ADIM * BDIM, HDIM / 32, COUT / 4);   // (128, 2, 8)

    conv4d_kernel<16><<<cgrid, 256, smem16>>>(image, w1, buf1);
    stats_kernel<<<COUT, 1024>>>(buf1, st1);
    normleaky_kernel<<<2048, 256>>>(buf1, st1, buf1);

    conv4d_kernel<32><<<cgrid, 256, smem32>>>(buf1, w2, buf2);
    stats_kernel<<<COUT, 1024>>>(buf2, st2);
    normleaky_kernel<<<2048, 256>>>(buf2, st2, out);
}